// round 3
// baseline (speedup 1.0000x reference)
#include <cuda_runtime.h>

#define TPB   128
#define U_MAX 128
#define MAX_BLOCKS 4096

// Scratch (no device allocation allowed -> __device__ globals, zero-init)
__device__ float        g_part_final[MAX_BLOCKS];
__device__ unsigned int g_counter;     // self-resetting per launch

// ---------------------------------------------------------------------------
// Single fused kernel.
//  prologue (per block; conn is 64KB, L2-resident after first touch):
//    w[j] = 3 * sum_i (conn[i][j] > 0.1 ? conn[i][j] : 0)
//  main (the 128MB stream): one float4 column per thread:
//    final[tn] = 0.5 * sum_j w[j]*unit[j][tn] + 1.5 * target[tn]
//  epilogue: deterministic per-block partial sum of final; last finished
//  block reduces partials, computes the boost scalar, and applies the
//  (normally inactive) boost path entirely on its own.
// ---------------------------------------------------------------------------
__global__ void __launch_bounds__(TPB)
kmain(const float4* __restrict__ conn4,   // conn as float4*, row stride 32
      const float4* __restrict__ unit,
      const float4* __restrict__ tgt,
      const float4* __restrict__ inspk,
      const float4* __restrict__ rb,
      float4* __restrict__ out,
      int TN4) {
    __shared__ float4 part[4][32];        // prologue row-partition partials
    __shared__ float  ws[U_MAX];
    __shared__ float  redf[TPB / 32];
    __shared__ int    s_last;
    __shared__ float  s_mean;
    __shared__ float  s_bs;

    const int t  = threadIdx.x;
    const int jc = t & 31;                // float4 column group within conn row
    const int rp = t >> 5;                // row partition (32 rows each)

    // --- fused w computation (32 independent loads/thread, full MLP) ---
    {
        float4 acc = make_float4(0.f, 0.f, 0.f, 0.f);
#pragma unroll
        for (int r = 0; r < 32; ++r) {
            float4 c = conn4[(rp * 32 + r) * 32 + jc];
            acc.x += (c.x > 0.1f) ? c.x : 0.0f;
            acc.y += (c.y > 0.1f) ? c.y : 0.0f;
            acc.z += (c.z > 0.1f) ? c.z : 0.0f;
            acc.w += (c.w > 0.1f) ? c.w : 0.0f;
        }
        part[rp][jc] = acc;
    }
    __syncthreads();
    if (t < 32) {
        float4 s = make_float4(0.f, 0.f, 0.f, 0.f);
#pragma unroll
        for (int r = 0; r < 4; ++r) {
            float4 p = part[r][t];
            s.x += p.x; s.y += p.y; s.z += p.z; s.w += p.w;
        }
        ws[t * 4 + 0] = 3.0f * s.x;
        ws[t * 4 + 1] = 3.0f * s.y;
        ws[t * 4 + 2] = 3.0f * s.z;
        ws[t * 4 + 3] = 3.0f * s.w;
    }
    __syncthreads();

    // --- 128 MB stream: one float4 column per thread ---
    const int idx = blockIdx.x * TPB + t;
    const float4* p = unit + idx;

    float4 acc = make_float4(0.f, 0.f, 0.f, 0.f);
#pragma unroll 16
    for (int j = 0; j < U_MAX; ++j) {
        float4 v = p[(size_t)j * TN4];
        float w = ws[j];
        acc.x = fmaf(w, v.x, acc.x);
        acc.y = fmaf(w, v.y, acc.y);
        acc.z = fmaf(w, v.z, acc.z);
        acc.w = fmaf(w, v.w, acc.w);
    }

    float4 tg = tgt[idx];
    float4 f;
    f.x = fmaf(tg.x, 1.5f, acc.x * 0.5f);
    f.y = fmaf(tg.y, 1.5f, acc.y * 0.5f);
    f.z = fmaf(tg.z, 1.5f, acc.z * 0.5f);
    f.w = fmaf(tg.w, 1.5f, acc.w * 0.5f);
    out[idx] = f;

    // --- deterministic per-block partial sum of final ---
    float lf = f.x + f.y + f.z + f.w;
#pragma unroll
    for (int o = 16; o > 0; o >>= 1)
        lf += __shfl_down_sync(0xFFFFFFFFu, lf, o);
    if ((t & 31) == 0) redf[t >> 5] = lf;
    __syncthreads();
    if (t == 0) {
        float a = redf[0] + redf[1] + redf[2] + redf[3];
        g_part_final[blockIdx.x] = a;
        __threadfence();
        unsigned v = atomicAdd(&g_counter, 1u);
        s_last = (v == gridDim.x - 1u) ? 1 : 0;
    }
    __syncthreads();
    if (!s_last) return;

    // ======================= last-block epilogue =======================
    __threadfence();
    const int nblocks = gridDim.x;
    float a = 0.f;
    for (int k = t; k < nblocks; k += TPB) a += __ldcg(&g_part_final[k]);
#pragma unroll
    for (int o = 16; o > 0; o >>= 1)
        a += __shfl_down_sync(0xFFFFFFFFu, a, o);
    if ((t & 31) == 0) redf[t >> 5] = a;
    __syncthreads();
    if (t == 0) {
        float TNf = (float)TN4 * 4.0f;
        s_mean = (redf[0] + redf[1] + redf[2] + redf[3]) / TNf;
    }
    __syncthreads();

    if (s_mean < 0.2f) {
        // Boost path (inactive for this data; correct if it triggers).
        // input_rate = mean(input_spikes) * 1000
        float li = 0.f;
        for (int k = t; k < TN4; k += TPB) {
            float4 v = inspk[k];
            li += v.x + v.y + v.z + v.w;
        }
#pragma unroll
        for (int o = 16; o > 0; o >>= 1)
            li += __shfl_down_sync(0xFFFFFFFFu, li, o);
        if ((t & 31) == 0) redf[t >> 5] = li;
        __syncthreads();
        if (t == 0) {
            float TNf = (float)TN4 * 4.0f;
            float input_rate = ((redf[0] + redf[1] + redf[2] + redf[3]) / TNf) * 1000.0f;
            float target_mean = (input_rate + 20.0f) * 0.01f;
            float boost = fmaxf(0.0f, target_mean - s_mean);
            s_bs = boost * 2.0f;
        }
        __syncthreads();
        float bs = s_bs;
        if (bs != 0.0f) {
            for (int k = t; k < TN4; k += TPB) {
                float4 r = rb[k];
                float4 o4 = __ldcg(&out[k]);
                o4.x = fmaf(r.x, bs, o4.x);
                o4.y = fmaf(r.y, bs, o4.y);
                o4.z = fmaf(r.z, bs, o4.z);
                o4.w = fmaf(r.w, bs, o4.w);
                out[k] = o4;
            }
        }
    }

    if (t == 0) g_counter = 0u;   // reset for next graph replay
}

// ---------------------------------------------------------------------------
// Launch
// Inputs (metadata order): input_spikes [T,N], unit_outputs [U,T,N],
// conn [U,U], target_spikes [T,N], rand_bias [T,N]. Output: [T,N] float32.
// ---------------------------------------------------------------------------
extern "C" void kernel_launch(void* const* d_in, const int* in_sizes, int n_in,
                              void* d_out, int out_size) {
    const float* inspk = (const float*)d_in[0];
    const float* unit  = (const float*)d_in[1];
    const float* conn  = (const float*)d_in[2];
    const float* tgt   = (const float*)d_in[3];
    const float* rb    = (const float*)d_in[4];
    float* out = (float*)d_out;

    int TN  = in_sizes[0];               // 262144
    int TN4 = TN / 4;                    // 65536
    int mb  = TN4 / TPB;                 // 512 blocks

    kmain<<<mb, TPB>>>((const float4*)conn, (const float4*)unit,
                       (const float4*)tgt, (const float4*)inspk,
                       (const float4*)rb, (float4*)out, TN4);
}

// round 4
// speedup vs baseline: 1.7130x; 1.7130x over previous
#include <cuda_runtime.h>

#define TPB   256
#define U_MAX 128
#define MAX_BLOCKS 4096

// Scratch (no device allocation allowed -> __device__ globals, zero-init)
__device__ float        g_part_final[MAX_BLOCKS];
__device__ unsigned int g_counter;     // self-resetting per launch

// ---------------------------------------------------------------------------
// Single fused kernel.
//  prologue (per block; conn is 64KB, L2-resident after first touch):
//    w[j] = 3 * sum_i (conn[i][j] > 0.1 ? conn[i][j] : 0)
//  main (the 128MB stream): one float4 column per thread, explicit 8-deep
//  load staging so 8 LDG.128 are in flight per thread (grid-limited occupancy
//  -> latency hiding must come from per-thread MLP).
//    final[tn] = 0.5 * sum_j w[j]*unit[j][tn] + 1.5 * target[tn]
//  epilogue: deterministic per-block partial sum of final; last finished
//  block computes the boost scalar and applies the (normally inactive)
//  boost path on its own.
// ---------------------------------------------------------------------------
__global__ void __launch_bounds__(TPB, 1)
kmain(const float4* __restrict__ conn4,   // conn as float4*, row stride 32
      const float4* __restrict__ unit,
      const float4* __restrict__ tgt,
      const float4* __restrict__ inspk,
      const float4* __restrict__ rb,
      float4* __restrict__ out,
      int TN4) {
    __shared__ float4 part[8][32];        // prologue row-partition partials
    __shared__ float  ws[U_MAX];
    __shared__ float  redf[TPB / 32];
    __shared__ int    s_last;
    __shared__ float  s_mean;
    __shared__ float  s_bs;

    const int t  = threadIdx.x;
    const int jc = t & 31;                // float4 column group within conn row
    const int rp = t >> 5;                // row partition (16 rows each)

    // --- fused w computation (16 independent L2 loads/thread) ---
    {
        float4 acc = make_float4(0.f, 0.f, 0.f, 0.f);
#pragma unroll
        for (int r = 0; r < 16; ++r) {
            float4 c = conn4[(rp * 16 + r) * 32 + jc];
            acc.x += (c.x > 0.1f) ? c.x : 0.0f;
            acc.y += (c.y > 0.1f) ? c.y : 0.0f;
            acc.z += (c.z > 0.1f) ? c.z : 0.0f;
            acc.w += (c.w > 0.1f) ? c.w : 0.0f;
        }
        part[rp][jc] = acc;
    }
    __syncthreads();
    if (t < 32) {
        float4 s = make_float4(0.f, 0.f, 0.f, 0.f);
#pragma unroll
        for (int r = 0; r < 8; ++r) {
            float4 p = part[r][t];
            s.x += p.x; s.y += p.y; s.z += p.z; s.w += p.w;
        }
        ws[t * 4 + 0] = 3.0f * s.x;
        ws[t * 4 + 1] = 3.0f * s.y;
        ws[t * 4 + 2] = 3.0f * s.z;
        ws[t * 4 + 3] = 3.0f * s.w;
    }
    __syncthreads();

    // --- 128 MB stream: explicit 8-deep staged loads, streaming hints ---
    const int idx = blockIdx.x * TPB + t;
    const float4* p = unit + idx;

    float4 acc = make_float4(0.f, 0.f, 0.f, 0.f);
#pragma unroll
    for (int j0 = 0; j0 < U_MAX; j0 += 8) {
        float4 v0 = __ldcs(p + (size_t)(j0 + 0) * TN4);
        float4 v1 = __ldcs(p + (size_t)(j0 + 1) * TN4);
        float4 v2 = __ldcs(p + (size_t)(j0 + 2) * TN4);
        float4 v3 = __ldcs(p + (size_t)(j0 + 3) * TN4);
        float4 v4 = __ldcs(p + (size_t)(j0 + 4) * TN4);
        float4 v5 = __ldcs(p + (size_t)(j0 + 5) * TN4);
        float4 v6 = __ldcs(p + (size_t)(j0 + 6) * TN4);
        float4 v7 = __ldcs(p + (size_t)(j0 + 7) * TN4);
        float w0 = ws[j0 + 0], w1 = ws[j0 + 1], w2 = ws[j0 + 2], w3 = ws[j0 + 3];
        float w4 = ws[j0 + 4], w5 = ws[j0 + 5], w6 = ws[j0 + 6], w7 = ws[j0 + 7];
        acc.x = fmaf(w0, v0.x, acc.x); acc.y = fmaf(w0, v0.y, acc.y);
        acc.z = fmaf(w0, v0.z, acc.z); acc.w = fmaf(w0, v0.w, acc.w);
        acc.x = fmaf(w1, v1.x, acc.x); acc.y = fmaf(w1, v1.y, acc.y);
        acc.z = fmaf(w1, v1.z, acc.z); acc.w = fmaf(w1, v1.w, acc.w);
        acc.x = fmaf(w2, v2.x, acc.x); acc.y = fmaf(w2, v2.y, acc.y);
        acc.z = fmaf(w2, v2.z, acc.z); acc.w = fmaf(w2, v2.w, acc.w);
        acc.x = fmaf(w3, v3.x, acc.x); acc.y = fmaf(w3, v3.y, acc.y);
        acc.z = fmaf(w3, v3.z, acc.z); acc.w = fmaf(w3, v3.w, acc.w);
        acc.x = fmaf(w4, v4.x, acc.x); acc.y = fmaf(w4, v4.y, acc.y);
        acc.z = fmaf(w4, v4.z, acc.z); acc.w = fmaf(w4, v4.w, acc.w);
        acc.x = fmaf(w5, v5.x, acc.x); acc.y = fmaf(w5, v5.y, acc.y);
        acc.z = fmaf(w5, v5.z, acc.z); acc.w = fmaf(w5, v5.w, acc.w);
        acc.x = fmaf(w6, v6.x, acc.x); acc.y = fmaf(w6, v6.y, acc.y);
        acc.z = fmaf(w6, v6.z, acc.z); acc.w = fmaf(w6, v6.w, acc.w);
        acc.x = fmaf(w7, v7.x, acc.x); acc.y = fmaf(w7, v7.y, acc.y);
        acc.z = fmaf(w7, v7.z, acc.z); acc.w = fmaf(w7, v7.w, acc.w);
    }

    float4 tg = __ldcs(tgt + idx);
    float4 f;
    f.x = fmaf(tg.x, 1.5f, acc.x * 0.5f);
    f.y = fmaf(tg.y, 1.5f, acc.y * 0.5f);
    f.z = fmaf(tg.z, 1.5f, acc.z * 0.5f);
    f.w = fmaf(tg.w, 1.5f, acc.w * 0.5f);
    __stcs(out + idx, f);

    // --- deterministic per-block partial sum of final ---
    float lf = f.x + f.y + f.z + f.w;
#pragma unroll
    for (int o = 16; o > 0; o >>= 1)
        lf += __shfl_down_sync(0xFFFFFFFFu, lf, o);
    if ((t & 31) == 0) redf[t >> 5] = lf;
    __syncthreads();
    if (t == 0) {
        float a = 0.f;
#pragma unroll
        for (int k = 0; k < TPB / 32; ++k) a += redf[k];
        g_part_final[blockIdx.x] = a;
        __threadfence();
        unsigned v = atomicAdd(&g_counter, 1u);
        s_last = (v == gridDim.x - 1u) ? 1 : 0;
    }
    __syncthreads();
    if (!s_last) return;

    // ======================= last-block epilogue =======================
    __threadfence();
    const int nblocks = gridDim.x;
    float a = 0.f;
    for (int k = t; k < nblocks; k += TPB) a += __ldcg(&g_part_final[k]);
#pragma unroll
    for (int o = 16; o > 0; o >>= 1)
        a += __shfl_down_sync(0xFFFFFFFFu, a, o);
    if ((t & 31) == 0) redf[t >> 5] = a;
    __syncthreads();
    if (t == 0) {
        float s = 0.f;
#pragma unroll
        for (int k = 0; k < TPB / 32; ++k) s += redf[k];
        s_mean = s / ((float)TN4 * 4.0f);
    }
    __syncthreads();

    if (s_mean < 0.2f) {
        // Boost path (inactive for this data; correct if it triggers).
        float li = 0.f;
        for (int k = t; k < TN4; k += TPB) {
            float4 v = inspk[k];
            li += v.x + v.y + v.z + v.w;
        }
#pragma unroll
        for (int o = 16; o > 0; o >>= 1)
            li += __shfl_down_sync(0xFFFFFFFFu, li, o);
        if ((t & 31) == 0) redf[t >> 5] = li;
        __syncthreads();
        if (t == 0) {
            float s = 0.f;
#pragma unroll
            for (int k = 0; k < TPB / 32; ++k) s += redf[k];
            float input_rate = (s / ((float)TN4 * 4.0f)) * 1000.0f;
            float target_mean = (input_rate + 20.0f) * 0.01f;
            float boost = fmaxf(0.0f, target_mean - s_mean);
            s_bs = boost * 2.0f;
        }
        __syncthreads();
        float bs = s_bs;
        if (bs != 0.0f) {
            for (int k = t; k < TN4; k += TPB) {
                float4 r = rb[k];
                float4 o4 = __ldcg(&out[k]);
                o4.x = fmaf(r.x, bs, o4.x);
                o4.y = fmaf(r.y, bs, o4.y);
                o4.z = fmaf(r.z, bs, o4.z);
                o4.w = fmaf(r.w, bs, o4.w);
                out[k] = o4;
            }
        }
    }

    if (t == 0) g_counter = 0u;   // reset for next graph replay
}

// ---------------------------------------------------------------------------
// Launch
// Inputs (metadata order): input_spikes [T,N], unit_outputs [U,T,N],
// conn [U,U], target_spikes [T,N], rand_bias [T,N]. Output: [T,N] float32.
// ---------------------------------------------------------------------------
extern "C" void kernel_launch(void* const* d_in, const int* in_sizes, int n_in,
                              void* d_out, int out_size) {
    const float* inspk = (const float*)d_in[0];
    const float* unit  = (const float*)d_in[1];
    const float* conn  = (const float*)d_in[2];
    const float* tgt   = (const float*)d_in[3];
    const float* rb    = (const float*)d_in[4];
    float* out = (float*)d_out;

    int TN  = in_sizes[0];               // 262144
    int TN4 = TN / 4;                    // 65536
    int mb  = TN4 / TPB;                 // 256 blocks

    kmain<<<mb, TPB>>>((const float4*)conn, (const float4*)unit,
                       (const float4*)tgt, (const float4*)inspk,
                       (const float4*)rb, (float4*)out, TN4);
}

// round 5
// speedup vs baseline: 1.8026x; 1.0523x over previous
#include <cuda_runtime.h>

#define TPB   128
#define U_MAX 128
#define MAX_BLOCKS 4096

// Scratch (no device allocation allowed -> __device__ globals, zero-init)
__device__ float        g_part_final[MAX_BLOCKS];
__device__ unsigned int g_counter;     // self-resetting per launch

// ---------------------------------------------------------------------------
// Single fused kernel. Geometry: 512 blocks x 128 threads, occ 4 CTA/SM ->
// 16 warps/SM, single wave over 148 SMs (512 <= 592 slots).
//  prologue (per block; conn 64KB, L2-resident after first touch):
//    w[j] = 3 * sum_i (conn[i][j] > 0.1 ? conn[i][j] : 0)
//  main (the 128MB stream): one float4 column per thread, explicit 8-deep
//  staged loads (8 LDG.128 in flight per thread), streaming cache hints.
//    final[tn] = 0.5 * sum_j w[j]*unit[j][tn] + 1.5 * target[tn]
//  epilogue: deterministic per-block partial sum; last finished block
//  computes the boost scalar and applies the (normally inactive) boost.
// ---------------------------------------------------------------------------
__global__ void __launch_bounds__(TPB, 4)
kmain(const float4* __restrict__ conn4,   // conn as float4*, row stride 32
      const float4* __restrict__ unit,
      const float4* __restrict__ tgt,
      const float4* __restrict__ inspk,
      const float4* __restrict__ rb,
      float4* __restrict__ out,
      int TN4) {
    __shared__ float4 part[4][32];        // prologue row-partition partials
    __shared__ float  ws[U_MAX];
    __shared__ float  redf[TPB / 32];
    __shared__ int    s_last;
    __shared__ float  s_mean;
    __shared__ float  s_bs;

    const int t  = threadIdx.x;
    const int jc = t & 31;                // float4 column group within conn row
    const int rp = t >> 5;                // row partition (32 rows each)

    // --- fused w computation (32 independent L2 loads/thread) ---
    {
        float4 acc = make_float4(0.f, 0.f, 0.f, 0.f);
#pragma unroll
        for (int r = 0; r < 32; ++r) {
            float4 c = conn4[(rp * 32 + r) * 32 + jc];
            acc.x += (c.x > 0.1f) ? c.x : 0.0f;
            acc.y += (c.y > 0.1f) ? c.y : 0.0f;
            acc.z += (c.z > 0.1f) ? c.z : 0.0f;
            acc.w += (c.w > 0.1f) ? c.w : 0.0f;
        }
        part[rp][jc] = acc;
    }
    __syncthreads();
    if (t < 32) {
        float4 s = make_float4(0.f, 0.f, 0.f, 0.f);
#pragma unroll
        for (int r = 0; r < 4; ++r) {
            float4 p = part[r][t];
            s.x += p.x; s.y += p.y; s.z += p.z; s.w += p.w;
        }
        ws[t * 4 + 0] = 3.0f * s.x;
        ws[t * 4 + 1] = 3.0f * s.y;
        ws[t * 4 + 2] = 3.0f * s.z;
        ws[t * 4 + 3] = 3.0f * s.w;
    }
    __syncthreads();

    // --- 128 MB stream: explicit 8-deep staged loads, streaming hints ---
    const int idx = blockIdx.x * TPB + t;
    const float4* p = unit + idx;

    float4 acc = make_float4(0.f, 0.f, 0.f, 0.f);
#pragma unroll
    for (int j0 = 0; j0 < U_MAX; j0 += 8) {
        float4 v0 = __ldcs(p + (size_t)(j0 + 0) * TN4);
        float4 v1 = __ldcs(p + (size_t)(j0 + 1) * TN4);
        float4 v2 = __ldcs(p + (size_t)(j0 + 2) * TN4);
        float4 v3 = __ldcs(p + (size_t)(j0 + 3) * TN4);
        float4 v4 = __ldcs(p + (size_t)(j0 + 4) * TN4);
        float4 v5 = __ldcs(p + (size_t)(j0 + 5) * TN4);
        float4 v6 = __ldcs(p + (size_t)(j0 + 6) * TN4);
        float4 v7 = __ldcs(p + (size_t)(j0 + 7) * TN4);
        float w0 = ws[j0 + 0], w1 = ws[j0 + 1], w2 = ws[j0 + 2], w3 = ws[j0 + 3];
        float w4 = ws[j0 + 4], w5 = ws[j0 + 5], w6 = ws[j0 + 6], w7 = ws[j0 + 7];
        acc.x = fmaf(w0, v0.x, acc.x); acc.y = fmaf(w0, v0.y, acc.y);
        acc.z = fmaf(w0, v0.z, acc.z); acc.w = fmaf(w0, v0.w, acc.w);
        acc.x = fmaf(w1, v1.x, acc.x); acc.y = fmaf(w1, v1.y, acc.y);
        acc.z = fmaf(w1, v1.z, acc.z); acc.w = fmaf(w1, v1.w, acc.w);
        acc.x = fmaf(w2, v2.x, acc.x); acc.y = fmaf(w2, v2.y, acc.y);
        acc.z = fmaf(w2, v2.z, acc.z); acc.w = fmaf(w2, v2.w, acc.w);
        acc.x = fmaf(w3, v3.x, acc.x); acc.y = fmaf(w3, v3.y, acc.y);
        acc.z = fmaf(w3, v3.z, acc.z); acc.w = fmaf(w3, v3.w, acc.w);
        acc.x = fmaf(w4, v4.x, acc.x); acc.y = fmaf(w4, v4.y, acc.y);
        acc.z = fmaf(w4, v4.z, acc.z); acc.w = fmaf(w4, v4.w, acc.w);
        acc.x = fmaf(w5, v5.x, acc.x); acc.y = fmaf(w5, v5.y, acc.y);
        acc.z = fmaf(w5, v5.z, acc.z); acc.w = fmaf(w5, v5.w, acc.w);
        acc.x = fmaf(w6, v6.x, acc.x); acc.y = fmaf(w6, v6.y, acc.y);
        acc.z = fmaf(w6, v6.z, acc.z); acc.w = fmaf(w6, v6.w, acc.w);
        acc.x = fmaf(w7, v7.x, acc.x); acc.y = fmaf(w7, v7.y, acc.y);
        acc.z = fmaf(w7, v7.z, acc.z); acc.w = fmaf(w7, v7.w, acc.w);
    }

    float4 tg = __ldcs(tgt + idx);
    float4 f;
    f.x = fmaf(tg.x, 1.5f, acc.x * 0.5f);
    f.y = fmaf(tg.y, 1.5f, acc.y * 0.5f);
    f.z = fmaf(tg.z, 1.5f, acc.z * 0.5f);
    f.w = fmaf(tg.w, 1.5f, acc.w * 0.5f);
    __stcs(out + idx, f);

    // --- deterministic per-block partial sum of final ---
    float lf = f.x + f.y + f.z + f.w;
#pragma unroll
    for (int o = 16; o > 0; o >>= 1)
        lf += __shfl_down_sync(0xFFFFFFFFu, lf, o);
    if ((t & 31) == 0) redf[t >> 5] = lf;
    __syncthreads();
    if (t == 0) {
        float a = 0.f;
#pragma unroll
        for (int k = 0; k < TPB / 32; ++k) a += redf[k];
        g_part_final[blockIdx.x] = a;
        __threadfence();
        unsigned v = atomicAdd(&g_counter, 1u);
        s_last = (v == gridDim.x - 1u) ? 1 : 0;
    }
    __syncthreads();
    if (!s_last) return;

    // ======================= last-block epilogue =======================
    __threadfence();
    const int nblocks = gridDim.x;
    float a = 0.f;
    for (int k = t; k < nblocks; k += TPB) a += __ldcg(&g_part_final[k]);
#pragma unroll
    for (int o = 16; o > 0; o >>= 1)
        a += __shfl_down_sync(0xFFFFFFFFu, a, o);
    if ((t & 31) == 0) redf[t >> 5] = a;
    __syncthreads();
    if (t == 0) {
        float s = 0.f;
#pragma unroll
        for (int k = 0; k < TPB / 32; ++k) s += redf[k];
        s_mean = s / ((float)TN4 * 4.0f);
    }
    __syncthreads();

    if (s_mean < 0.2f) {
        // Boost path (inactive for this data; correct if it triggers).
        float li = 0.f;
        for (int k = t; k < TN4; k += TPB) {
            float4 v = inspk[k];
            li += v.x + v.y + v.z + v.w;
        }
#pragma unroll
        for (int o = 16; o > 0; o >>= 1)
            li += __shfl_down_sync(0xFFFFFFFFu, li, o);
        if ((t & 31) == 0) redf[t >> 5] = li;
        __syncthreads();
        if (t == 0) {
            float s = 0.f;
#pragma unroll
            for (int k = 0; k < TPB / 32; ++k) s += redf[k];
            float input_rate = (s / ((float)TN4 * 4.0f)) * 1000.0f;
            float target_mean = (input_rate + 20.0f) * 0.01f;
            float boost = fmaxf(0.0f, target_mean - s_mean);
            s_bs = boost * 2.0f;
        }
        __syncthreads();
        float bs = s_bs;
        if (bs != 0.0f) {
            for (int k = t; k < TN4; k += TPB) {
                float4 r = rb[k];
                float4 o4 = __ldcg(&out[k]);
                o4.x = fmaf(r.x, bs, o4.x);
                o4.y = fmaf(r.y, bs, o4.y);
                o4.z = fmaf(r.z, bs, o4.z);
                o4.w = fmaf(r.w, bs, o4.w);
                out[k] = o4;
            }
        }
    }

    if (t == 0) g_counter = 0u;   // reset for next graph replay
}

// ---------------------------------------------------------------------------
// Launch
// Inputs (metadata order): input_spikes [T,N], unit_outputs [U,T,N],
// conn [U,U], target_spikes [T,N], rand_bias [T,N]. Output: [T,N] float32.
// ---------------------------------------------------------------------------
extern "C" void kernel_launch(void* const* d_in, const int* in_sizes, int n_in,
                              void* d_out, int out_size) {
    const float* inspk = (const float*)d_in[0];
    const float* unit  = (const float*)d_in[1];
    const float* conn  = (const float*)d_in[2];
    const float* tgt   = (const float*)d_in[3];
    const float* rb    = (const float*)d_in[4];
    float* out = (float*)d_out;

    int TN  = in_sizes[0];               // 262144
    int TN4 = TN / 4;                    // 65536
    int mb  = TN4 / TPB;                 // 512 blocks

    kmain<<<mb, TPB>>>((const float4*)conn, (const float4*)unit,
                       (const float4*)tgt, (const float4*)inspk,
                       (const float4*)rb, (float4*)out, TN4);
}

// round 6
// speedup vs baseline: 1.8302x; 1.0153x over previous
#include <cuda_runtime.h>

#define TPB   128
#define U_MAX 128
#define MAX_BLOCKS 4096

// Scratch (no device allocation allowed -> __device__ globals, zero-init)
__device__ float        g_part_final[MAX_BLOCKS];
__device__ unsigned int g_counter;     // self-resetting per launch

// ---------------------------------------------------------------------------
// Single fused kernel. Geometry: 512 blocks x 128 threads, 4 CTA/SM ->
// 16 warps/SM, single wave over 148 SMs.
//  prologue (per block; conn 64KB, L2-resident after first touch):
//    w[j] = 3 * sum_i (conn[i][j] > 0.1 ? conn[i][j] : 0)
//  main (the 128MB stream): one float4 column per thread; manual
//  double-buffered prefetch (group k+1 loads issued BEFORE group k FMAs)
//  so the memory pipe never drains behind the FMA bursts.
//    final[tn] = 0.5 * sum_j w[j]*unit[j][tn] + 1.5 * target[tn]
//  epilogue: deterministic per-block partial sum; last finished block
//  computes the boost scalar and applies the (normally inactive) boost.
// ---------------------------------------------------------------------------
__global__ void __launch_bounds__(TPB, 4)
kmain(const float4* __restrict__ conn4,   // conn as float4*, row stride 32
      const float4* __restrict__ unit,
      const float4* __restrict__ tgt,
      const float4* __restrict__ inspk,
      const float4* __restrict__ rb,
      float4* __restrict__ out,
      int TN4) {
    __shared__ float4 part[4][32];        // prologue row-partition partials
    __shared__ float  ws[U_MAX];
    __shared__ float  redf[TPB / 32];
    __shared__ int    s_last;
    __shared__ float  s_mean;
    __shared__ float  s_bs;

    const int t  = threadIdx.x;
    const int jc = t & 31;                // float4 column group within conn row
    const int rp = t >> 5;                // row partition (32 rows each)

    // --- fused w computation (32 independent L2 loads/thread) ---
    {
        float4 acc = make_float4(0.f, 0.f, 0.f, 0.f);
#pragma unroll
        for (int r = 0; r < 32; ++r) {
            float4 c = conn4[(rp * 32 + r) * 32 + jc];
            acc.x += (c.x > 0.1f) ? c.x : 0.0f;
            acc.y += (c.y > 0.1f) ? c.y : 0.0f;
            acc.z += (c.z > 0.1f) ? c.z : 0.0f;
            acc.w += (c.w > 0.1f) ? c.w : 0.0f;
        }
        part[rp][jc] = acc;
    }
    __syncthreads();
    if (t < 32) {
        float4 s = make_float4(0.f, 0.f, 0.f, 0.f);
#pragma unroll
        for (int r = 0; r < 4; ++r) {
            float4 p = part[r][t];
            s.x += p.x; s.y += p.y; s.z += p.z; s.w += p.w;
        }
        ws[t * 4 + 0] = 3.0f * s.x;
        ws[t * 4 + 1] = 3.0f * s.y;
        ws[t * 4 + 2] = 3.0f * s.z;
        ws[t * 4 + 3] = 3.0f * s.w;
    }
    __syncthreads();

    // --- 128 MB stream: double-buffered 8-deep prefetch pipeline ---
    const int idx = blockIdx.x * TPB + t;
    const float4* p = unit + idx;

    float4 buf[8];
#pragma unroll
    for (int k = 0; k < 8; ++k)
        buf[k] = __ldcs(p + (size_t)k * TN4);

    float4 acc = make_float4(0.f, 0.f, 0.f, 0.f);
#pragma unroll
    for (int j0 = 0; j0 < U_MAX; j0 += 8) {
        float4 nxt[8];
        if (j0 + 8 < U_MAX) {
#pragma unroll
            for (int k = 0; k < 8; ++k)
                nxt[k] = __ldcs(p + (size_t)(j0 + 8 + k) * TN4);
        }
#pragma unroll
        for (int k = 0; k < 8; ++k) {
            float w = ws[j0 + k];
            acc.x = fmaf(w, buf[k].x, acc.x);
            acc.y = fmaf(w, buf[k].y, acc.y);
            acc.z = fmaf(w, buf[k].z, acc.z);
            acc.w = fmaf(w, buf[k].w, acc.w);
        }
        if (j0 + 8 < U_MAX) {
#pragma unroll
            for (int k = 0; k < 8; ++k)
                buf[k] = nxt[k];
        }
    }

    float4 tg = __ldcs(tgt + idx);
    float4 f;
    f.x = fmaf(tg.x, 1.5f, acc.x * 0.5f);
    f.y = fmaf(tg.y, 1.5f, acc.y * 0.5f);
    f.z = fmaf(tg.z, 1.5f, acc.z * 0.5f);
    f.w = fmaf(tg.w, 1.5f, acc.w * 0.5f);
    __stcs(out + idx, f);

    // --- deterministic per-block partial sum of final ---
    float lf = f.x + f.y + f.z + f.w;
#pragma unroll
    for (int o = 16; o > 0; o >>= 1)
        lf += __shfl_down_sync(0xFFFFFFFFu, lf, o);
    if ((t & 31) == 0) redf[t >> 5] = lf;
    __syncthreads();
    if (t == 0) {
        float a = 0.f;
#pragma unroll
        for (int k = 0; k < TPB / 32; ++k) a += redf[k];
        g_part_final[blockIdx.x] = a;
        __threadfence();
        unsigned v = atomicAdd(&g_counter, 1u);
        s_last = (v == gridDim.x - 1u) ? 1 : 0;
    }
    __syncthreads();
    if (!s_last) return;

    // ======================= last-block epilogue =======================
    __threadfence();
    const int nblocks = gridDim.x;
    float a = 0.f;
    for (int k = t; k < nblocks; k += TPB) a += __ldcg(&g_part_final[k]);
#pragma unroll
    for (int o = 16; o > 0; o >>= 1)
        a += __shfl_down_sync(0xFFFFFFFFu, a, o);
    if ((t & 31) == 0) redf[t >> 5] = a;
    __syncthreads();
    if (t == 0) {
        float s = 0.f;
#pragma unroll
        for (int k = 0; k < TPB / 32; ++k) s += redf[k];
        s_mean = s / ((float)TN4 * 4.0f);
    }
    __syncthreads();

    if (s_mean < 0.2f) {
        // Boost path (inactive for this data; correct if it triggers).
        float li = 0.f;
        for (int k = t; k < TN4; k += TPB) {
            float4 v = inspk[k];
            li += v.x + v.y + v.z + v.w;
        }
#pragma unroll
        for (int o = 16; o > 0; o >>= 1)
            li += __shfl_down_sync(0xFFFFFFFFu, li, o);
        if ((t & 31) == 0) redf[t >> 5] = li;
        __syncthreads();
        if (t == 0) {
            float s = 0.f;
#pragma unroll
            for (int k = 0; k < TPB / 32; ++k) s += redf[k];
            float input_rate = (s / ((float)TN4 * 4.0f)) * 1000.0f;
            float target_mean = (input_rate + 20.0f) * 0.01f;
            float boost = fmaxf(0.0f, target_mean - s_mean);
            s_bs = boost * 2.0f;
        }
        __syncthreads();
        float bs = s_bs;
        if (bs != 0.0f) {
            for (int k = t; k < TN4; k += TPB) {
                float4 r = rb[k];
                float4 o4 = __ldcg(&out[k]);
                o4.x = fmaf(r.x, bs, o4.x);
                o4.y = fmaf(r.y, bs, o4.y);
                o4.z = fmaf(r.z, bs, o4.z);
                o4.w = fmaf(r.w, bs, o4.w);
                out[k] = o4;
            }
        }
    }

    if (t == 0) g_counter = 0u;   // reset for next graph replay
}

// ---------------------------------------------------------------------------
// Launch
// Inputs (metadata order): input_spikes [T,N], unit_outputs [U,T,N],
// conn [U,U], target_spikes [T,N], rand_bias [T,N]. Output: [T,N] float32.
// ---------------------------------------------------------------------------
extern "C" void kernel_launch(void* const* d_in, const int* in_sizes, int n_in,
                              void* d_out, int out_size) {
    const float* inspk = (const float*)d_in[0];
    const float* unit  = (const float*)d_in[1];
    const float* conn  = (const float*)d_in[2];
    const float* tgt   = (const float*)d_in[3];
    const float* rb    = (const float*)d_in[4];
    float* out = (float*)d_out;

    int TN  = in_sizes[0];               // 262144
    int TN4 = TN / 4;                    // 65536
    int mb  = TN4 / TPB;                 // 512 blocks

    kmain<<<mb, TPB>>>((const float4*)conn, (const float4*)unit,
                       (const float4*)tgt, (const float4*)inspk,
                       (const float4*)rb, (float4*)out, TN4);
}